// round 13
// baseline (speedup 1.0000x reference)
#include <cuda_runtime.h>
#include <cuda_bf16.h>
#include <cstdint>

// Problem constants (fixed shapes from setup_inputs)
static constexpr int kB  = 8;
static constexpr int kLC = 2048;
static constexpr int kLQ = 1024;
static constexpr int kD  = 768;
static constexpr float kScale = 0.036084391824351615f; // 1/sqrt(768)

// ---------------------------------------------------------------------------
// Scratch (__device__ globals; no allocs allowed) — pure bf16 pipeline
// ---------------------------------------------------------------------------
__device__ __nv_bfloat16 g_ctx_hi [(size_t)kB * kLC * kD];
__device__ __nv_bfloat16 g_qh_pk  [(size_t)kB * kLQ * kD];   // PACKED valid qh rows
__device__ __nv_bfloat16 g_qhT_hi [(size_t)kB * kD * kLQ];   // PACKED transposed
__device__ __nv_bfloat16 g_W_hi   [(size_t)kD * kD];
__device__ __nv_bfloat16 g_q_hi   [(size_t)kB * kLQ * kD];   // projected query (packed rows)
__device__ float         g_scores [(size_t)kB * kLC * kLQ];  // packed cols
__device__ __nv_bfloat16 g_p_hi   [(size_t)kB * kLC * kLQ];  // packed probs
__device__ int           g_qvalid [kB * kLQ];                // packed->orig q
__device__ int           g_Lv     [kB];                      // valid count per batch

// ---------------------------------------------------------------------------
// PTX helpers — base sm_103 instructions only (NO tcgen05 in this toolchain)
// ---------------------------------------------------------------------------
__device__ __forceinline__ uint32_t smem_u32(const void* p) {
    uint32_t a;
    asm("{ .reg .u64 t; cvta.to.shared.u64 t, %1; cvt.u32.u64 %0, t; }" : "=r"(a) : "l"(p));
    return a;
}
__device__ __forceinline__ void cp16(uint32_t dst, const void* src) {
    asm volatile("cp.async.cg.shared.global [%0], [%1], 16;" :: "r"(dst), "l"(src) : "memory");
}
__device__ __forceinline__ void cp_commit() { asm volatile("cp.async.commit_group;" ::: "memory"); }
template<int N> __device__ __forceinline__ void cp_wait() {
    asm volatile("cp.async.wait_group %0;" :: "n"(N) : "memory");
}
__device__ __forceinline__ void ldm4(uint32_t* r, uint32_t addr) {
    asm volatile("ldmatrix.sync.aligned.m8n8.x4.shared.b16 {%0,%1,%2,%3}, [%4];"
                 : "=r"(r[0]), "=r"(r[1]), "=r"(r[2]), "=r"(r[3]) : "r"(addr));
}
__device__ __forceinline__ void mma_bf16(float* c, const uint32_t* a, uint32_t b0, uint32_t b1) {
    asm volatile("mma.sync.aligned.m16n8k16.row.col.f32.bf16.bf16.f32 "
                 "{%0,%1,%2,%3}, {%4,%5,%6,%7}, {%8,%9}, {%0,%1,%2,%3};"
                 : "+f"(c[0]), "+f"(c[1]), "+f"(c[2]), "+f"(c[3])
                 : "r"(a[0]), "r"(a[1]), "r"(a[2]), "r"(a[3]), "r"(b0), "r"(b1));
}

// ---------------------------------------------------------------------------
// Tensor-core NT GEMM, single-term bf16, fp32 accumulate: acc = A*B^T
// CTA tile 256x128, 512 threads, 16 warps (8M x 2N), warp tile 32x64.
// BK=32, 4-stage cp.async pipeline; stage = (256+128)*80B = 30KB; 120KB smem,
// 1 CTA/SM. Same compute/SM/stage as the 128x128 2-CTA config but 25% less
// L2 traffic per stage (A reused across twice the FLOPs).
// MODE 0 (K1): batched A; M-early-exit at pad128(Lv[z]); +bias; out -> bf16
// MODE 1 (K2): N-early-exit at Lv[z]; out=acc*scale fp32
// MODE 2 (K4): runtime K=pad128(Lv[z]); out=acc fp32 at [.., coff+col]
// ---------------------------------------------------------------------------
static constexpr int A_ROWS  = 256;
static constexpr int B_ROWS  = 128;
static constexpr int A_B     = A_ROWS * 80;            // 20480
static constexpr int STAGE_B = (A_ROWS + B_ROWS) * 80; // 30720
static constexpr int NSTAGE  = 4;
static constexpr int SMEM_SZ = NSTAGE * STAGE_B;       // 122880

template<int MODE>
__global__ void __launch_bounds__(512, 1)
gemm_tc(const __nv_bfloat16* __restrict__ Ahi, long sA, int lda,
        const __nv_bfloat16* __restrict__ Bhi, long sB, int ldb, int Kstatic,
        float* __restrict__ Cf, long sC, int ldc, int coff, float scale,
        const float* __restrict__ bias,
        __nv_bfloat16* __restrict__ Chi, long sQ, int ldq,
        const int* __restrict__ LvArr)
{
    const int z  = blockIdx.z;
    const int m0 = blockIdx.y * 256;
    const int n0 = blockIdx.x * 128;

    const int lv = __ldg(&LvArr[z]);
    if (MODE == 0 && m0 >= ((lv + 127) & ~127)) return;   // only packed query rows
    if (MODE == 1 && n0 >= lv) return;                    // only valid q columns

    int Ktot = Kstatic;
    if (MODE == 2) Ktot = (lv + 127) & ~127;

    extern __shared__ __align__(128) char dsm[];
    const uint32_t base = smem_u32(dsm);

    const int tid  = threadIdx.x;
    const int wid  = tid >> 5;
    const int lane = tid & 31;
    const int wm   = wid & 7;          // 8 warp rows of 32
    const int wn   = wid >> 3;         // 2 warp cols of 64

    const __nv_bfloat16* pAh = Ahi + (long)z * sA + (long)m0 * lda;
    const __nv_bfloat16* pBh = Bhi + (long)z * sB + (long)n0 * ldb;

    const int S = Ktot >> 5;           // BK=32 stages (>=4 always)

    auto load_stage = [&](int s) {
        const uint32_t sb = base + (uint32_t)(s & (NSTAGE - 1)) * STAGE_B;
        const int k0 = s << 5;
        const int r  = tid >> 2;       // 0..127
        const int ch = tid & 3;        // 16B chunk within 64B row
        cp16(sb + r * 80 + ch * 16,         pAh + (long)r * lda + k0 + ch * 8);
        cp16(sb + (r + 128) * 80 + ch * 16, pAh + (long)(r + 128) * lda + k0 + ch * 8);
        cp16(sb + A_B + r * 80 + ch * 16,   pBh + (long)r * ldb + k0 + ch * 8);
        cp_commit();
    };

    // ldmatrix per-lane address components
    const int ati = lane >> 3;
    const int a_row = (lane & 7) + (ati & 1) * 8;
    const int a_col = (ati >> 1) * 16;
    const uint32_t a_base = (uint32_t)((wm * 32 + a_row) * 80 + a_col);
    const int b_row = (ati >> 1) * 8 + (lane & 7);
    const int b_col = (ati & 1) * 16;
    const uint32_t b_base = (uint32_t)(A_B + (wn * 64 + b_row) * 80 + b_col);

    float acc[2][8][4];
    #pragma unroll
    for (int mt = 0; mt < 2; mt++)
        #pragma unroll
        for (int nt = 0; nt < 8; nt++)
            #pragma unroll
            for (int r = 0; r < 4; r++) acc[mt][nt][r] = 0.f;

    load_stage(0);
    load_stage(1);
    load_stage(2);

    for (int s = 0; s < S; s++) {
        const int rem = S - 1 - s;
        if (rem >= 2) cp_wait<2>(); else if (rem == 1) cp_wait<1>(); else cp_wait<0>();
        __syncthreads();                    // single barrier per stage
        if (s + 3 < S) load_stage(s + 3);

        const uint32_t sb = base + (uint32_t)(s & (NSTAGE - 1)) * STAGE_B;
        #pragma unroll
        for (int ks = 0; ks < 2; ks++) {
            uint32_t ah[2][4];
            #pragma unroll
            for (int mt = 0; mt < 2; mt++)
                ldm4(ah[mt], sb + a_base + (uint32_t)(mt * 16 * 80 + ks * 32));
            uint32_t bh[4][4];
            #pragma unroll
            for (int np = 0; np < 4; np++)
                ldm4(bh[np], sb + b_base + (uint32_t)(np * 16 * 80 + ks * 32));
            #pragma unroll
            for (int mt = 0; mt < 2; mt++)
                #pragma unroll
                for (int nt = 0; nt < 8; nt++) {
                    const int np = nt >> 1, ps = (nt & 1) * 2;
                    mma_bf16(acc[mt][nt], ah[mt], bh[np][ps], bh[np][ps + 1]);
                }
        }
    }

    // Epilogue
    const int g = lane >> 2, t = lane & 3;
    #pragma unroll
    for (int mt = 0; mt < 2; mt++) {
        const int r0 = m0 + wm * 32 + mt * 16 + g;
        #pragma unroll
        for (int nt = 0; nt < 8; nt++) {
            const int col = n0 + wn * 64 + nt * 8 + 2 * t;
            float v0 = acc[mt][nt][0], v1 = acc[mt][nt][1];
            float v2 = acc[mt][nt][2], v3 = acc[mt][nt][3];
            if (MODE != 0) {
                float* d0 = Cf + (long)z * sC + (long)r0 * ldc + coff + col;
                float* d1 = d0 + (long)8 * ldc;
                *reinterpret_cast<float2*>(d0) = make_float2(v0 * scale, v1 * scale);
                *reinterpret_cast<float2*>(d1) = make_float2(v2 * scale, v3 * scale);
            } else {
                const float2 bv = *reinterpret_cast<const float2*>(bias + col);
                __nv_bfloat162 p0, p1;
                p0.x = __float2bfloat16(v0 + bv.x); p0.y = __float2bfloat16(v1 + bv.y);
                p1.x = __float2bfloat16(v2 + bv.x); p1.y = __float2bfloat16(v3 + bv.y);
                __nv_bfloat16* dh0 = Chi + (long)z * sQ + (long)r0 * ldq + col;
                *reinterpret_cast<__nv_bfloat162*>(dh0) = p0;
                *reinterpret_cast<__nv_bfloat162*>(dh0 + 8 * ldq) = p1;
            }
        }
    }
}

// ---------------------------------------------------------------------------
// Per-batch mask prefix scan: qvalid (packed->orig) and Lv.
// ---------------------------------------------------------------------------
__global__ void mask_scan(const int* __restrict__ qm,
                          int* __restrict__ qvalid, int* __restrict__ Lv)
{
    const int b = blockIdx.x, t = threadIdx.x;
    __shared__ int sc[256];
    const int* m = qm + (long)b * kLQ;
    int mv[4];
    #pragma unroll
    for (int i = 0; i < 4; i++) mv[i] = m[t * 4 + i];
    const int c = mv[0] + mv[1] + mv[2] + mv[3];
    sc[t] = c;
    __syncthreads();
    for (int off = 1; off < 256; off <<= 1) {
        const int v = (t >= off) ? sc[t - off] : 0;
        __syncthreads();
        sc[t] += v;
        __syncthreads();
    }
    int exc = sc[t] - c;
    int* qv = qvalid + (long)b * kLQ;
    #pragma unroll
    for (int i = 0; i < 4; i++) {
        const int q = t * 4 + i;
        if (mv[i]) { qv[exc] = q; exc++; }
    }
    if (t == 255) Lv[b] = sc[255];
}

// ---------------------------------------------------------------------------
// qh -> (a) packed bf16 rows [B, packed_q, D]   (K1's A operand)
//       (b) packed transposed [B, D, packed_q]  (K4's B operand)
// ---------------------------------------------------------------------------
__global__ void gather_pack(const float* __restrict__ in,
                            const int* __restrict__ qvalid,
                            const int* __restrict__ LvArr,
                            __nv_bfloat16* __restrict__ pk,
                            __nv_bfloat16* __restrict__ oT)
{
    const int b  = blockIdx.z;
    const int lv = __ldg(&LvArr[b]);
    const int q0 = blockIdx.y * 32;               // packed row tile
    if (q0 >= ((lv + 127) & ~127)) return;
    const int d0 = blockIdx.x * 32;
    const int tx = threadIdx.x, ty = threadIdx.y;

    __shared__ float t[32][33];
    __shared__ int src[32];
    if (ty == 0) {
        const int j = q0 + tx;
        src[tx] = (j < lv) ? __ldg(&qvalid[b * kLQ + j]) : -1;
    }
    __syncthreads();

    const float* ib = in + (long)b * kLQ * kD;
    __nv_bfloat16* pb = pk + (long)b * kLQ * kD;
    #pragma unroll
    for (int j = 0; j < 4; j++) {
        const int row = ty + 8 * j;               // packed row within tile
        const int sq  = src[row];
        const float v = (sq >= 0) ? ib[(long)sq * kD + d0 + tx] : 0.f;
        t[row][tx] = v;
        pb[(long)(q0 + row) * kD + d0 + tx] = __float2bfloat16(v);
    }
    __syncthreads();
    __nv_bfloat16* bh = oT + (long)b * kD * kLQ;
    #pragma unroll
    for (int j = 0; j < 4; j++) {
        const float v = t[tx][ty + 8 * j];
        bh[(long)(d0 + ty + 8 * j) * kLQ + q0 + tx] = __float2bfloat16(v);
    }
}

// ---------------------------------------------------------------------------
// ctx: one read -> output first half copy + bf16 convert
// ---------------------------------------------------------------------------
__global__ void prep_ctx(const float* __restrict__ ctx, float* __restrict__ out,
                         __nv_bfloat16* __restrict__ hi)
{
    const int n4 = kB * kLC * (kD / 4);
    const int i = blockIdx.x * blockDim.x + threadIdx.x;
    if (i >= n4) return;
    const float4 v = reinterpret_cast<const float4*>(ctx)[i];
    const int row = i / (kD / 4);
    const int col = i - row * (kD / 4);
    reinterpret_cast<float4*>(out)[(long)row * (2 * kD / 4) + col] = v;
    __nv_bfloat162 p0; p0.x = __float2bfloat16(v.x); p0.y = __float2bfloat16(v.y);
    __nv_bfloat162 p1; p1.x = __float2bfloat16(v.z); p1.y = __float2bfloat16(v.w);
    reinterpret_cast<__nv_bfloat162*>(hi)[2*i+0] = p0;
    reinterpret_cast<__nv_bfloat162*>(hi)[2*i+1] = p1;
}

// ---------------------------------------------------------------------------
// fp32 -> bf16 convert (W)
// ---------------------------------------------------------------------------
__global__ void split_hi(const float* __restrict__ in,
                         __nv_bfloat16* __restrict__ hi, int n4)
{
    const int i = blockIdx.x * blockDim.x + threadIdx.x;
    if (i >= n4) return;
    const float4 v = reinterpret_cast<const float4*>(in)[i];
    __nv_bfloat162 p0; p0.x = __float2bfloat16(v.x); p0.y = __float2bfloat16(v.y);
    __nv_bfloat162 p1; p1.x = __float2bfloat16(v.z); p1.y = __float2bfloat16(v.w);
    reinterpret_cast<__nv_bfloat162*>(hi)[2*i+0] = p0;
    reinterpret_cast<__nv_bfloat162*>(hi)[2*i+1] = p1;
}

// ---------------------------------------------------------------------------
// Softmax over packed columns [0, Lv); writes p_hi zeros in [Lv, pad128(Lv)).
// ---------------------------------------------------------------------------
__global__ void softmax_packed(const float* __restrict__ scores,
                               const int* __restrict__ LvArr,
                               __nv_bfloat16* __restrict__ phi)
{
    const int row = blockIdx.x;              // 0 .. B*LC-1
    const int b   = row >> 11;               // / kLC
    const int lv  = __ldg(&LvArr[b]);
    const int lim = (lv + 127) & ~127;
    const float* s = scores + (long)row * kLQ;

    const int t = threadIdx.x;               // 256 threads, 4 elems each
    float v[4]; int ok[4];
    float mx = -1e30f;
    #pragma unroll
    for (int i = 0; i < 4; i++) {
        const int q = t + i * 256;
        ok[i] = (q < lv);
        v[i]  = ok[i] ? s[q] : 0.f;
        if (ok[i]) mx = fmaxf(mx, v[i]);
    }

    __shared__ float smax[8];
    __shared__ float ssum[8];

    #pragma unroll
    for (int off = 16; off; off >>= 1)
        mx = fmaxf(mx, __shfl_xor_sync(0xffffffffu, mx, off));
    if ((t & 31) == 0) smax[t >> 5] = mx;
    __syncthreads();
    float bm = -1e30f;
    #pragma unroll
    for (int w = 0; w < 8; w++) bm = fmaxf(bm, smax[w]);

    float e[4];
    float sum = 0.f;
    #pragma unroll
    for (int i = 0; i < 4; i++) {
        e[i] = ok[i] ? __expf(v[i] - bm) : 0.f;
        sum += e[i];
    }
    #pragma unroll
    for (int off = 16; off; off >>= 1)
        sum += __shfl_xor_sync(0xffffffffu, sum, off);
    if ((t & 31) == 0) ssum[t >> 5] = sum;
    __syncthreads();
    float total = 0.f;
    #pragma unroll
    for (int w = 0; w < 8; w++) total += ssum[w];

    const float inv = 1.f / total;
    __nv_bfloat16* dh = phi + (long)row * kLQ;
    #pragma unroll
    for (int i = 0; i < 4; i++) {
        const int q = t + i * 256;
        if (q < lim) dh[q] = __float2bfloat16(e[i] * inv);   // 0 for q in [lv, lim)
    }
}

// ---------------------------------------------------------------------------
extern "C" void kernel_launch(void* const* d_in, const int* in_sizes, int n_in,
                              void* d_out, int out_size)
{
    const float* ctx  = (const float*)d_in[0];
    const float* qh   = (const float*)d_in[2];
    const int*   qm   = (const int*)d_in[3];
    const float* W    = (const float*)d_in[4];
    const float* bias = (const float*)d_in[5];
    float* out = (float*)d_out;
    (void)in_sizes; (void)n_in; (void)out_size;

    __nv_bfloat16 *ctx_hi, *qh_pk, *qhT_hi, *W_hi, *q_hi, *p_hi;
    float* scores;
    int *qvalid, *Lv;
    cudaGetSymbolAddress((void**)&ctx_hi, g_ctx_hi);
    cudaGetSymbolAddress((void**)&qh_pk,  g_qh_pk);
    cudaGetSymbolAddress((void**)&qhT_hi, g_qhT_hi);
    cudaGetSymbolAddress((void**)&W_hi,   g_W_hi);
    cudaGetSymbolAddress((void**)&q_hi,   g_q_hi);
    cudaGetSymbolAddress((void**)&p_hi,   g_p_hi);
    cudaGetSymbolAddress((void**)&scores, g_scores);
    cudaGetSymbolAddress((void**)&qvalid, g_qvalid);
    cudaGetSymbolAddress((void**)&Lv,     g_Lv);

    // One-time resource setup (first call is the uncaptured correctness run;
    // captured calls then only record/wait on these — pure graph nodes).
    static cudaStream_t s1 = nullptr;
    static cudaEvent_t eFork = nullptr, eW = nullptr, eJoin = nullptr;
    if (s1 == nullptr) {
        cudaStreamCreateWithFlags(&s1, cudaStreamNonBlocking);
        cudaEventCreateWithFlags(&eFork, cudaEventDisableTiming);
        cudaEventCreateWithFlags(&eW,    cudaEventDisableTiming);
        cudaEventCreateWithFlags(&eJoin, cudaEventDisableTiming);
        cudaFuncSetAttribute(gemm_tc<0>, cudaFuncAttributeMaxDynamicSharedMemorySize, SMEM_SZ);
        cudaFuncSetAttribute(gemm_tc<1>, cudaFuncAttributeMaxDynamicSharedMemorySize, SMEM_SZ);
        cudaFuncSetAttribute(gemm_tc<2>, cudaFuncAttributeMaxDynamicSharedMemorySize, SMEM_SZ);
    }

    // Fork: side stream runs W convert then the ctx branch.
    cudaEventRecord(eFork, 0);
    cudaStreamWaitEvent(s1, eFork, 0);

    // Branch B (stream s1): W convert (tiny), then ctx copy+convert (HBM-bound).
    split_hi<<<(kD * kD / 4 + 255) / 256, 256, 0, s1>>>(W, W_hi, kD * kD / 4);
    cudaEventRecord(eW, s1);
    prep_ctx<<<(kB * kLC * (kD / 4) + 255) / 256, 256, 0, s1>>>(ctx, out, ctx_hi);
    cudaEventRecord(eJoin, s1);

    // Branch A (main stream): mask scan, qh gather/transpose, K1 (needs W).
    mask_scan<<<kB, 256>>>(qm, qvalid, Lv);
    gather_pack<<<dim3(kD / 32, kLQ / 32, kB), dim3(32, 8)>>>(qh, qvalid, Lv, qh_pk, qhT_hi);
    cudaStreamWaitEvent(0, eW, 0);
    gemm_tc<0><<<dim3(kD / 128, kLQ / 256, kB), 512, SMEM_SZ>>>(
        qh_pk, (long)kLQ * kD, kD,
        W_hi, 0, kD, kD,
        nullptr, 0, 0, 0, 1.0f, bias,
        q_hi, (long)kLQ * kD, kD, Lv);

    // Join: K2 needs both ctx_hi (branch B) and q_hi (branch A).
    cudaStreamWaitEvent(0, eJoin, 0);

    // K2: packed scores = scale * ctx_hi @ q_hi^T (N-early-exit at Lv)
    gemm_tc<1><<<dim3(kLQ / 128, kLC / 256, kB), 512, SMEM_SZ>>>(
        ctx_hi, (long)kLC * kD, kD,
        q_hi, (long)kLQ * kD, kD, kD,
        scores, (long)kLC * kLQ, kLQ, 0, kScale, nullptr,
        nullptr, 0, 0, Lv);
    // softmax -> p_hi (zeros in pad region)
    softmax_packed<<<kB * kLC, 256>>>(scores, Lv, p_hi);
    // K4: out[:, D:] = p_hi @ qhT_hi^T (runtime K = pad128(Lv))
    gemm_tc<2><<<dim3(kD / 128, kLC / 256, kB), 512, SMEM_SZ>>>(
        p_hi, (long)kLC * kLQ, kLQ,
        qhT_hi, (long)kD * kLQ, kLQ, 0,
        out, (long)kLC * 2 * kD, 2 * kD, kD, 1.0f, nullptr,
        nullptr, 0, 0, Lv);
}

// round 15
// speedup vs baseline: 1.0628x; 1.0628x over previous
#include <cuda_runtime.h>
#include <cuda_bf16.h>
#include <cstdint>

// Problem constants (fixed shapes from setup_inputs)
static constexpr int kB  = 8;
static constexpr int kLC = 2048;
static constexpr int kLQ = 1024;
static constexpr int kD  = 768;
static constexpr float kScale = 0.036084391824351615f; // 1/sqrt(768)

// ---------------------------------------------------------------------------
// Scratch (__device__ globals; no allocs allowed) — pure bf16 pipeline
// ---------------------------------------------------------------------------
__device__ __nv_bfloat16 g_ctx_hi [(size_t)kB * kLC * kD];
__device__ __nv_bfloat16 g_qh_pk  [(size_t)kB * kLQ * kD];   // PACKED valid qh rows
__device__ __nv_bfloat16 g_qhT_hi [(size_t)kB * kD * kLQ];   // PACKED transposed
__device__ __nv_bfloat16 g_W_hi   [(size_t)kD * kD];
__device__ __nv_bfloat16 g_q_hi   [(size_t)kB * kLQ * kD];   // projected query (packed rows)
__device__ __nv_bfloat16 g_scores [(size_t)kB * kLC * kLQ];  // packed cols, bf16
__device__ __nv_bfloat16 g_p_hi   [(size_t)kB * kLC * kLQ];  // packed probs
__device__ int           g_qvalid [kB * kLQ];                // packed->orig q
__device__ int           g_Lv     [kB];                      // valid count per batch

// ---------------------------------------------------------------------------
// PTX helpers — base sm_103 instructions only (NO tcgen05 in this toolchain)
// ---------------------------------------------------------------------------
__device__ __forceinline__ uint32_t smem_u32(const void* p) {
    uint32_t a;
    asm("{ .reg .u64 t; cvta.to.shared.u64 t, %1; cvt.u32.u64 %0, t; }" : "=r"(a) : "l"(p));
    return a;
}
__device__ __forceinline__ void cp16(uint32_t dst, const void* src) {
    asm volatile("cp.async.cg.shared.global [%0], [%1], 16;" :: "r"(dst), "l"(src) : "memory");
}
__device__ __forceinline__ void cp_commit() { asm volatile("cp.async.commit_group;" ::: "memory"); }
template<int N> __device__ __forceinline__ void cp_wait() {
    asm volatile("cp.async.wait_group %0;" :: "n"(N) : "memory");
}
__device__ __forceinline__ void ldm4(uint32_t* r, uint32_t addr) {
    asm volatile("ldmatrix.sync.aligned.m8n8.x4.shared.b16 {%0,%1,%2,%3}, [%4];"
                 : "=r"(r[0]), "=r"(r[1]), "=r"(r[2]), "=r"(r[3]) : "r"(addr));
}
__device__ __forceinline__ void mma_bf16(float* c, const uint32_t* a, uint32_t b0, uint32_t b1) {
    asm volatile("mma.sync.aligned.m16n8k16.row.col.f32.bf16.bf16.f32 "
                 "{%0,%1,%2,%3}, {%4,%5,%6,%7}, {%8,%9}, {%0,%1,%2,%3};"
                 : "+f"(c[0]), "+f"(c[1]), "+f"(c[2]), "+f"(c[3])
                 : "r"(a[0]), "r"(a[1]), "r"(a[2]), "r"(a[3]), "r"(b0), "r"(b1));
}

// ---------------------------------------------------------------------------
// Tensor-core NT GEMM, single-term bf16, fp32 accumulate: acc = A*B^T
// CTA tile 128x128, BK=32, 4-stage cp.async pipeline (2 arrays/stage = 80KB),
// 8 warps (4Mx2N), warp tile 32x64, 2 CTAs/SM, ONE barrier per stage.
// (Proven optimum: R12 5-stage and R13 256x128 variants both regressed.)
// MODE 0 (K1): batched A; M-early-exit at pad128(Lv[z]); +bias; out -> bf16
// MODE 1 (K2): N-early-exit at Lv[z]; out = bf16(acc*scale) -> Chi (scores)
// MODE 2 (K4): runtime K=pad128(Lv[z]); out=acc fp32 at [.., coff+col]
// ---------------------------------------------------------------------------
static constexpr int ARR_B   = 10240;      // 128 rows * 80B (64B data + 16B pad)
static constexpr int STAGE_B = 2 * ARR_B;  // A, B
static constexpr int NSTAGE  = 4;
static constexpr int SMEM_SZ = NSTAGE * STAGE_B;  // 81920

template<int MODE>
__global__ void __launch_bounds__(256, 2)
gemm_tc(const __nv_bfloat16* __restrict__ Ahi, long sA, int lda,
        const __nv_bfloat16* __restrict__ Bhi, long sB, int ldb, int Kstatic,
        float* __restrict__ Cf, long sC, int ldc, int coff, float scale,
        const float* __restrict__ bias,
        __nv_bfloat16* __restrict__ Chi, long sQ, int ldq,
        const int* __restrict__ LvArr)
{
    const int z  = blockIdx.z;
    const int m0 = blockIdx.y * 128;
    const int n0 = blockIdx.x * 128;

    const int lv = __ldg(&LvArr[z]);
    if (MODE == 0 && m0 >= ((lv + 127) & ~127)) return;   // only packed query rows
    if (MODE == 1 && n0 >= lv) return;                    // only valid q columns

    int Ktot = Kstatic;
    if (MODE == 2) Ktot = (lv + 127) & ~127;

    extern __shared__ __align__(128) char dsm[];
    const uint32_t base = smem_u32(dsm);

    const int tid  = threadIdx.x;
    const int wid  = tid >> 5;
    const int lane = tid & 31;
    const int wm   = wid & 3;
    const int wn   = wid >> 2;

    const __nv_bfloat16* pAh = Ahi + (long)z * sA + (long)m0 * lda;
    const __nv_bfloat16* pBh = Bhi + (long)z * sB + (long)n0 * ldb;

    const int S = Ktot >> 5;           // BK=32 stages (>=4 always)

    auto load_stage = [&](int s) {
        const uint32_t sb = base + (uint32_t)(s & (NSTAGE - 1)) * STAGE_B;
        const int k0 = s << 5;
        const int r  = tid >> 2;
        const int ch = tid & 3;
        cp16(sb + r * 80 + ch * 16,        pAh + (long)r * lda + k0 + ch * 8);
        cp16(sb + (r + 64) * 80 + ch * 16, pAh + (long)(r + 64) * lda + k0 + ch * 8);
        cp16(sb + ARR_B + r * 80 + ch * 16,        pBh + (long)r * ldb + k0 + ch * 8);
        cp16(sb + ARR_B + (r + 64) * 80 + ch * 16, pBh + (long)(r + 64) * ldb + k0 + ch * 8);
        cp_commit();
    };

    // ldmatrix per-lane address components
    const int ati = lane >> 3;
    const int a_row = (lane & 7) + (ati & 1) * 8;
    const int a_col = (ati >> 1) * 16;
    const uint32_t a_base = (uint32_t)((wm * 32 + a_row) * 80 + a_col);
    const int b_row = (ati >> 1) * 8 + (lane & 7);
    const int b_col = (ati & 1) * 16;
    const uint32_t b_base = (uint32_t)((wn * 64 + b_row) * 80 + b_col);

    float acc[2][8][4];
    #pragma unroll
    for (int mt = 0; mt < 2; mt++)
        #pragma unroll
        for (int nt = 0; nt < 8; nt++)
            #pragma unroll
            for (int r = 0; r < 4; r++) acc[mt][nt][r] = 0.f;

    load_stage(0);
    load_stage(1);
    load_stage(2);

    for (int s = 0; s < S; s++) {
        const int rem = S - 1 - s;
        if (rem >= 2) cp_wait<2>(); else if (rem == 1) cp_wait<1>(); else cp_wait<0>();
        __syncthreads();                    // single barrier per stage
        if (s + 3 < S) load_stage(s + 3);

        const uint32_t sb = base + (uint32_t)(s & (NSTAGE - 1)) * STAGE_B;
        #pragma unroll
        for (int ks = 0; ks < 2; ks++) {
            uint32_t ah[2][4];
            #pragma unroll
            for (int mt = 0; mt < 2; mt++)
                ldm4(ah[mt], sb + a_base + (uint32_t)(mt * 16 * 80 + ks * 32));
            uint32_t bh[4][4];
            #pragma unroll
            for (int np = 0; np < 4; np++)
                ldm4(bh[np], sb + ARR_B + b_base + (uint32_t)(np * 16 * 80 + ks * 32));
            #pragma unroll
            for (int mt = 0; mt < 2; mt++)
                #pragma unroll
                for (int nt = 0; nt < 8; nt++) {
                    const int np = nt >> 1, ps = (nt & 1) * 2;
                    mma_bf16(acc[mt][nt], ah[mt], bh[np][ps], bh[np][ps + 1]);
                }
        }
    }

    // Epilogue
    const int g = lane >> 2, t = lane & 3;
    #pragma unroll
    for (int mt = 0; mt < 2; mt++) {
        const int r0 = m0 + wm * 32 + mt * 16 + g;
        #pragma unroll
        for (int nt = 0; nt < 8; nt++) {
            const int col = n0 + wn * 64 + nt * 8 + 2 * t;
            float v0 = acc[mt][nt][0], v1 = acc[mt][nt][1];
            float v2 = acc[mt][nt][2], v3 = acc[mt][nt][3];
            if (MODE == 2) {
                float* d0 = Cf + (long)z * sC + (long)r0 * ldc + coff + col;
                float* d1 = d0 + (long)8 * ldc;
                *reinterpret_cast<float2*>(d0) = make_float2(v0, v1);
                *reinterpret_cast<float2*>(d1) = make_float2(v2, v3);
            } else if (MODE == 1) {
                // bf16 scores (scaled)
                __nv_bfloat162 p0, p1;
                p0.x = __float2bfloat16(v0 * scale); p0.y = __float2bfloat16(v1 * scale);
                p1.x = __float2bfloat16(v2 * scale); p1.y = __float2bfloat16(v3 * scale);
                __nv_bfloat16* dh0 = Chi + (long)z * sQ + (long)r0 * ldq + col;
                *reinterpret_cast<__nv_bfloat162*>(dh0) = p0;
                *reinterpret_cast<__nv_bfloat162*>(dh0 + 8 * ldq) = p1;
            } else {
                const float2 bv = *reinterpret_cast<const float2*>(bias + col);
                __nv_bfloat162 p0, p1;
                p0.x = __float2bfloat16(v0 + bv.x); p0.y = __float2bfloat16(v1 + bv.y);
                p1.x = __float2bfloat16(v2 + bv.x); p1.y = __float2bfloat16(v3 + bv.y);
                __nv_bfloat16* dh0 = Chi + (long)z * sQ + (long)r0 * ldq + col;
                *reinterpret_cast<__nv_bfloat162*>(dh0) = p0;
                *reinterpret_cast<__nv_bfloat162*>(dh0 + 8 * ldq) = p1;
            }
        }
    }
}

// ---------------------------------------------------------------------------
// Per-batch mask prefix scan: qvalid (packed->orig) and Lv.
// ---------------------------------------------------------------------------
__global__ void mask_scan(const int* __restrict__ qm,
                          int* __restrict__ qvalid, int* __restrict__ Lv)
{
    const int b = blockIdx.x, t = threadIdx.x;
    __shared__ int sc[256];
    const int* m = qm + (long)b * kLQ;
    int mv[4];
    #pragma unroll
    for (int i = 0; i < 4; i++) mv[i] = m[t * 4 + i];
    const int c = mv[0] + mv[1] + mv[2] + mv[3];
    sc[t] = c;
    __syncthreads();
    for (int off = 1; off < 256; off <<= 1) {
        const int v = (t >= off) ? sc[t - off] : 0;
        __syncthreads();
        sc[t] += v;
        __syncthreads();
    }
    int exc = sc[t] - c;
    int* qv = qvalid + (long)b * kLQ;
    #pragma unroll
    for (int i = 0; i < 4; i++) {
        const int q = t * 4 + i;
        if (mv[i]) { qv[exc] = q; exc++; }
    }
    if (t == 255) Lv[b] = sc[255];
}

// ---------------------------------------------------------------------------
// qh -> (a) packed bf16 rows [B, packed_q, D]   (K1's A operand)
//       (b) packed transposed [B, D, packed_q]  (K4's B operand)
// ---------------------------------------------------------------------------
__global__ void gather_pack(const float* __restrict__ in,
                            const int* __restrict__ qvalid,
                            const int* __restrict__ LvArr,
                            __nv_bfloat16* __restrict__ pk,
                            __nv_bfloat16* __restrict__ oT)
{
    const int b  = blockIdx.z;
    const int lv = __ldg(&LvArr[b]);
    const int q0 = blockIdx.y * 32;               // packed row tile
    if (q0 >= ((lv + 127) & ~127)) return;
    const int d0 = blockIdx.x * 32;
    const int tx = threadIdx.x, ty = threadIdx.y;

    __shared__ float t[32][33];
    __shared__ int src[32];
    if (ty == 0) {
        const int j = q0 + tx;
        src[tx] = (j < lv) ? __ldg(&qvalid[b * kLQ + j]) : -1;
    }
    __syncthreads();

    const float* ib = in + (long)b * kLQ * kD;
    __nv_bfloat16* pb = pk + (long)b * kLQ * kD;
    #pragma unroll
    for (int j = 0; j < 4; j++) {
        const int row = ty + 8 * j;               // packed row within tile
        const int sq  = src[row];
        const float v = (sq >= 0) ? ib[(long)sq * kD + d0 + tx] : 0.f;
        t[row][tx] = v;
        pb[(long)(q0 + row) * kD + d0 + tx] = __float2bfloat16(v);
    }
    __syncthreads();
    __nv_bfloat16* bh = oT + (long)b * kD * kLQ;
    #pragma unroll
    for (int j = 0; j < 4; j++) {
        const float v = t[tx][ty + 8 * j];
        bh[(long)(d0 + ty + 8 * j) * kLQ + q0 + tx] = __float2bfloat16(v);
    }
}

// ---------------------------------------------------------------------------
// ctx: one read -> output first half copy + bf16 convert
// ---------------------------------------------------------------------------
__global__ void prep_ctx(const float* __restrict__ ctx, float* __restrict__ out,
                         __nv_bfloat16* __restrict__ hi)
{
    const int n4 = kB * kLC * (kD / 4);
    const int i = blockIdx.x * blockDim.x + threadIdx.x;
    if (i >= n4) return;
    const float4 v = reinterpret_cast<const float4*>(ctx)[i];
    const int row = i / (kD / 4);
    const int col = i - row * (kD / 4);
    reinterpret_cast<float4*>(out)[(long)row * (2 * kD / 4) + col] = v;
    __nv_bfloat162 p0; p0.x = __float2bfloat16(v.x); p0.y = __float2bfloat16(v.y);
    __nv_bfloat162 p1; p1.x = __float2bfloat16(v.z); p1.y = __float2bfloat16(v.w);
    reinterpret_cast<__nv_bfloat162*>(hi)[2*i+0] = p0;
    reinterpret_cast<__nv_bfloat162*>(hi)[2*i+1] = p1;
}

// ---------------------------------------------------------------------------
// fp32 -> bf16 convert (W)
// ---------------------------------------------------------------------------
__global__ void split_hi(const float* __restrict__ in,
                         __nv_bfloat16* __restrict__ hi, int n4)
{
    const int i = blockIdx.x * blockDim.x + threadIdx.x;
    if (i >= n4) return;
    const float4 v = reinterpret_cast<const float4*>(in)[i];
    __nv_bfloat162 p0; p0.x = __float2bfloat16(v.x); p0.y = __float2bfloat16(v.y);
    __nv_bfloat162 p1; p1.x = __float2bfloat16(v.z); p1.y = __float2bfloat16(v.w);
    reinterpret_cast<__nv_bfloat162*>(hi)[2*i+0] = p0;
    reinterpret_cast<__nv_bfloat162*>(hi)[2*i+1] = p1;
}

// ---------------------------------------------------------------------------
// Softmax over packed bf16 scores [0, Lv); writes p_hi zeros in [Lv, pad128).
// ---------------------------------------------------------------------------
__global__ void softmax_packed(const __nv_bfloat16* __restrict__ scores,
                               const int* __restrict__ LvArr,
                               __nv_bfloat16* __restrict__ phi)
{
    const int row = blockIdx.x;              // 0 .. B*LC-1
    const int b   = row >> 11;               // / kLC
    const int lv  = __ldg(&LvArr[b]);
    const int lim = (lv + 127) & ~127;
    const __nv_bfloat16* s = scores + (long)row * kLQ;

    const int t = threadIdx.x;               // 256 threads, 4 elems each
    float v[4]; int ok[4];
    float mx = -1e30f;
    #pragma unroll
    for (int i = 0; i < 4; i++) {
        const int q = t + i * 256;
        ok[i] = (q < lv);
        v[i]  = ok[i] ? __bfloat162float(s[q]) : 0.f;
        if (ok[i]) mx = fmaxf(mx, v[i]);
    }

    __shared__ float smax[8];
    __shared__ float ssum[8];

    #pragma unroll
    for (int off = 16; off; off >>= 1)
        mx = fmaxf(mx, __shfl_xor_sync(0xffffffffu, mx, off));
    if ((t & 31) == 0) smax[t >> 5] = mx;
    __syncthreads();
    float bm = -1e30f;
    #pragma unroll
    for (int w = 0; w < 8; w++) bm = fmaxf(bm, smax[w]);

    float e[4];
    float sum = 0.f;
    #pragma unroll
    for (int i = 0; i < 4; i++) {
        e[i] = ok[i] ? __expf(v[i] - bm) : 0.f;
        sum += e[i];
    }
    #pragma unroll
    for (int off = 16; off; off >>= 1)
        sum += __shfl_xor_sync(0xffffffffu, sum, off);
    if ((t & 31) == 0) ssum[t >> 5] = sum;
    __syncthreads();
    float total = 0.f;
    #pragma unroll
    for (int w = 0; w < 8; w++) total += ssum[w];

    const float inv = 1.f / total;
    __nv_bfloat16* dh = phi + (long)row * kLQ;
    #pragma unroll
    for (int i = 0; i < 4; i++) {
        const int q = t + i * 256;
        if (q < lim) dh[q] = __float2bfloat16(e[i] * inv);   // 0 for q in [lv, lim)
    }
}

// ---------------------------------------------------------------------------
extern "C" void kernel_launch(void* const* d_in, const int* in_sizes, int n_in,
                              void* d_out, int out_size)
{
    const float* ctx  = (const float*)d_in[0];
    const float* qh   = (const float*)d_in[2];
    const int*   qm   = (const int*)d_in[3];
    const float* W    = (const float*)d_in[4];
    const float* bias = (const float*)d_in[5];
    float* out = (float*)d_out;
    (void)in_sizes; (void)n_in; (void)out_size;

    __nv_bfloat16 *ctx_hi, *qh_pk, *qhT_hi, *W_hi, *q_hi, *p_hi, *scores;
    int *qvalid, *Lv;
    cudaGetSymbolAddress((void**)&ctx_hi, g_ctx_hi);
    cudaGetSymbolAddress((void**)&qh_pk,  g_qh_pk);
    cudaGetSymbolAddress((void**)&qhT_hi, g_qhT_hi);
    cudaGetSymbolAddress((void**)&W_hi,   g_W_hi);
    cudaGetSymbolAddress((void**)&q_hi,   g_q_hi);
    cudaGetSymbolAddress((void**)&p_hi,   g_p_hi);
    cudaGetSymbolAddress((void**)&scores, g_scores);
    cudaGetSymbolAddress((void**)&qvalid, g_qvalid);
    cudaGetSymbolAddress((void**)&Lv,     g_Lv);

    // One-time resource setup (first call is the uncaptured correctness run;
    // captured calls then only record/wait on these — pure graph nodes).
    static cudaStream_t s1 = nullptr;
    static cudaEvent_t eFork = nullptr, eW = nullptr, eJoin = nullptr;
    if (s1 == nullptr) {
        cudaStreamCreateWithFlags(&s1, cudaStreamNonBlocking);
        cudaEventCreateWithFlags(&eFork, cudaEventDisableTiming);
        cudaEventCreateWithFlags(&eW,    cudaEventDisableTiming);
        cudaEventCreateWithFlags(&eJoin, cudaEventDisableTiming);
        cudaFuncSetAttribute(gemm_tc<0>, cudaFuncAttributeMaxDynamicSharedMemorySize, SMEM_SZ);
        cudaFuncSetAttribute(gemm_tc<1>, cudaFuncAttributeMaxDynamicSharedMemorySize, SMEM_SZ);
        cudaFuncSetAttribute(gemm_tc<2>, cudaFuncAttributeMaxDynamicSharedMemorySize, SMEM_SZ);
    }

    // Fork: side stream runs W convert then the ctx branch.
    cudaEventRecord(eFork, 0);
    cudaStreamWaitEvent(s1, eFork, 0);

    // Branch B (stream s1): W convert (tiny), then ctx copy+convert (HBM-bound).
    split_hi<<<(kD * kD / 4 + 255) / 256, 256, 0, s1>>>(W, W_hi, kD * kD / 4);
    cudaEventRecord(eW, s1);
    prep_ctx<<<(kB * kLC * (kD / 4) + 255) / 256, 256, 0, s1>>>(ctx, out, ctx_hi);
    cudaEventRecord(eJoin, s1);

    // Branch A (main stream): mask scan, qh gather/transpose, K1 (needs W).
    mask_scan<<<kB, 256>>>(qm, qvalid, Lv);
    gather_pack<<<dim3(kD / 32, kLQ / 32, kB), dim3(32, 8)>>>(qh, qvalid, Lv, qh_pk, qhT_hi);
    cudaStreamWaitEvent(0, eW, 0);
    gemm_tc<0><<<dim3(kD / 128, kLQ / 128, kB), 256, SMEM_SZ>>>(
        qh_pk, (long)kLQ * kD, kD,
        W_hi, 0, kD, kD,
        nullptr, 0, 0, 0, 1.0f, bias,
        q_hi, (long)kLQ * kD, kD, Lv);

    // Join: K2 needs both ctx_hi (branch B) and q_hi (branch A).
    cudaStreamWaitEvent(0, eJoin, 0);

    // K2: packed bf16 scores = bf16(scale * ctx_hi @ q_hi^T)  (N-early-exit)
    gemm_tc<1><<<dim3(kLQ / 128, kLC / 128, kB), 256, SMEM_SZ>>>(
        ctx_hi, (long)kLC * kD, kD,
        q_hi, (long)kLQ * kD, kD, kD,
        nullptr, 0, 0, 0, kScale, nullptr,
        scores, (long)kLC * kLQ, kLQ, Lv);
    // softmax over bf16 scores -> p_hi (zeros in pad region)
    softmax_packed<<<kB * kLC, 256>>>(scores, Lv, p_hi);
    // K4: out[:, D:] = p_hi @ qhT_hi^T (runtime K = pad128(Lv))
    gemm_tc<2><<<dim3(kD / 128, kLC / 128, kB), 256, SMEM_SZ>>>(
        p_hi, (long)kLC * kLQ, kLQ,
        qhT_hi, (long)kD * kLQ, kLQ, 0,
        out, (long)kLC * 2 * kD, 2 * kD, kD, 1.0f, nullptr,
        nullptr, 0, 0, Lv);
}

// round 16
// speedup vs baseline: 1.1239x; 1.0576x over previous
#include <cuda_runtime.h>
#include <cuda_bf16.h>
#include <cstdint>

// Problem constants (fixed shapes from setup_inputs)
static constexpr int kB  = 8;
static constexpr int kLC = 2048;
static constexpr int kLQ = 1024;
static constexpr int kD  = 768;
static constexpr float kScale = 0.036084391824351615f; // 1/sqrt(768)

// ---------------------------------------------------------------------------
// Scratch (__device__ globals; no allocs allowed) — pure bf16 pipeline
// ---------------------------------------------------------------------------
__device__ __nv_bfloat16 g_ctx_hi [(size_t)kB * kLC * kD];
__device__ __nv_bfloat16 g_qh_pk  [(size_t)kB * kLQ * kD];   // PACKED valid qh rows
__device__ __nv_bfloat16 g_qhT_hi [(size_t)kB * kD * kLQ];   // PACKED transposed
__device__ __nv_bfloat16 g_W_hi   [(size_t)kD * kD];
__device__ __nv_bfloat16 g_q_hi   [(size_t)kB * kLQ * kD];   // projected query (packed rows)
__device__ __nv_bfloat16 g_scores [(size_t)kB * kLC * kLQ];  // packed cols, bf16
__device__ __nv_bfloat16 g_p_hi   [(size_t)kB * kLC * kLQ];  // packed probs
__device__ int           g_qvalid [kB * kLQ];                // packed->orig q
__device__ int           g_Lv     [kB];                      // valid count per batch

// ---------------------------------------------------------------------------
// PTX helpers — base sm_103 instructions only (NO tcgen05 in this toolchain)
// ---------------------------------------------------------------------------
__device__ __forceinline__ uint32_t smem_u32(const void* p) {
    uint32_t a;
    asm("{ .reg .u64 t; cvta.to.shared.u64 t, %1; cvt.u32.u64 %0, t; }" : "=r"(a) : "l"(p));
    return a;
}
__device__ __forceinline__ void cp16(uint32_t dst, const void* src) {
    asm volatile("cp.async.cg.shared.global [%0], [%1], 16;" :: "r"(dst), "l"(src) : "memory");
}
__device__ __forceinline__ void cp_commit() { asm volatile("cp.async.commit_group;" ::: "memory"); }
template<int N> __device__ __forceinline__ void cp_wait() {
    asm volatile("cp.async.wait_group %0;" :: "n"(N) : "memory");
}
__device__ __forceinline__ void ldm4(uint32_t* r, uint32_t addr) {
    asm volatile("ldmatrix.sync.aligned.m8n8.x4.shared.b16 {%0,%1,%2,%3}, [%4];"
                 : "=r"(r[0]), "=r"(r[1]), "=r"(r[2]), "=r"(r[3]) : "r"(addr));
}
__device__ __forceinline__ void mma_bf16(float* c, const uint32_t* a, uint32_t b0, uint32_t b1) {
    asm volatile("mma.sync.aligned.m16n8k16.row.col.f32.bf16.bf16.f32 "
                 "{%0,%1,%2,%3}, {%4,%5,%6,%7}, {%8,%9}, {%0,%1,%2,%3};"
                 : "+f"(c[0]), "+f"(c[1]), "+f"(c[2]), "+f"(c[3])
                 : "r"(a[0]), "r"(a[1]), "r"(a[2]), "r"(a[3]), "r"(b0), "r"(b1));
}

// ---------------------------------------------------------------------------
// Tensor-core NT GEMM, single-term bf16, fp32 accumulate: acc = A*B^T
// CTA tile 128x128, BK=32, 4-stage cp.async pipeline (2 arrays/stage = 80KB),
// 8 warps (4Mx2N), warp tile 32x64, 2 CTAs/SM, ONE barrier per stage.
// Batch offset handled by caller via pointer + LvArr offsets (dual-chain).
// MODE 0 (K1): batched A; M-early-exit at pad128(Lv[z]); +bias; out -> bf16
// MODE 1 (K2): N-early-exit at Lv[z]; out = bf16(acc*scale) -> Chi (scores)
// MODE 2 (K4): runtime K=pad128(Lv[z]); out=acc fp32 at [.., coff+col]
// ---------------------------------------------------------------------------
static constexpr int ARR_B   = 10240;      // 128 rows * 80B (64B data + 16B pad)
static constexpr int STAGE_B = 2 * ARR_B;  // A, B
static constexpr int NSTAGE  = 4;
static constexpr int SMEM_SZ = NSTAGE * STAGE_B;  // 81920

template<int MODE>
__global__ void __launch_bounds__(256, 2)
gemm_tc(const __nv_bfloat16* __restrict__ Ahi, long sA, int lda,
        const __nv_bfloat16* __restrict__ Bhi, long sB, int ldb, int Kstatic,
        float* __restrict__ Cf, long sC, int ldc, int coff, float scale,
        const float* __restrict__ bias,
        __nv_bfloat16* __restrict__ Chi, long sQ, int ldq,
        const int* __restrict__ LvArr)
{
    const int z  = blockIdx.z;
    const int m0 = blockIdx.y * 128;
    const int n0 = blockIdx.x * 128;

    const int lv = __ldg(&LvArr[z]);
    if (MODE == 0 && m0 >= ((lv + 127) & ~127)) return;   // only packed query rows
    if (MODE == 1 && n0 >= lv) return;                    // only valid q columns

    int Ktot = Kstatic;
    if (MODE == 2) Ktot = (lv + 127) & ~127;

    extern __shared__ __align__(128) char dsm[];
    const uint32_t base = smem_u32(dsm);

    const int tid  = threadIdx.x;
    const int wid  = tid >> 5;
    const int lane = tid & 31;
    const int wm   = wid & 3;
    const int wn   = wid >> 2;

    const __nv_bfloat16* pAh = Ahi + (long)z * sA + (long)m0 * lda;
    const __nv_bfloat16* pBh = Bhi + (long)z * sB + (long)n0 * ldb;

    const int S = Ktot >> 5;           // BK=32 stages (>=4 always)

    auto load_stage = [&](int s) {
        const uint32_t sb = base + (uint32_t)(s & (NSTAGE - 1)) * STAGE_B;
        const int k0 = s << 5;
        const int r  = tid >> 2;
        const int ch = tid & 3;
        cp16(sb + r * 80 + ch * 16,        pAh + (long)r * lda + k0 + ch * 8);
        cp16(sb + (r + 64) * 80 + ch * 16, pAh + (long)(r + 64) * lda + k0 + ch * 8);
        cp16(sb + ARR_B + r * 80 + ch * 16,        pBh + (long)r * ldb + k0 + ch * 8);
        cp16(sb + ARR_B + (r + 64) * 80 + ch * 16, pBh + (long)(r + 64) * ldb + k0 + ch * 8);
        cp_commit();
    };

    // ldmatrix per-lane address components
    const int ati = lane >> 3;
    const int a_row = (lane & 7) + (ati & 1) * 8;
    const int a_col = (ati >> 1) * 16;
    const uint32_t a_base = (uint32_t)((wm * 32 + a_row) * 80 + a_col);
    const int b_row = (ati >> 1) * 8 + (lane & 7);
    const int b_col = (ati & 1) * 16;
    const uint32_t b_base = (uint32_t)((wn * 64 + b_row) * 80 + b_col);

    float acc[2][8][4];
    #pragma unroll
    for (int mt = 0; mt < 2; mt++)
        #pragma unroll
        for (int nt = 0; nt < 8; nt++)
            #pragma unroll
            for (int r = 0; r < 4; r++) acc[mt][nt][r] = 0.f;

    load_stage(0);
    load_stage(1);
    load_stage(2);

    for (int s = 0; s < S; s++) {
        const int rem = S - 1 - s;
        if (rem >= 2) cp_wait<2>(); else if (rem == 1) cp_wait<1>(); else cp_wait<0>();
        __syncthreads();                    // single barrier per stage
        if (s + 3 < S) load_stage(s + 3);

        const uint32_t sb = base + (uint32_t)(s & (NSTAGE - 1)) * STAGE_B;
        #pragma unroll
        for (int ks = 0; ks < 2; ks++) {
            uint32_t ah[2][4];
            #pragma unroll
            for (int mt = 0; mt < 2; mt++)
                ldm4(ah[mt], sb + a_base + (uint32_t)(mt * 16 * 80 + ks * 32));
            uint32_t bh[4][4];
            #pragma unroll
            for (int np = 0; np < 4; np++)
                ldm4(bh[np], sb + ARR_B + b_base + (uint32_t)(np * 16 * 80 + ks * 32));
            #pragma unroll
            for (int mt = 0; mt < 2; mt++)
                #pragma unroll
                for (int nt = 0; nt < 8; nt++) {
                    const int np = nt >> 1, ps = (nt & 1) * 2;
                    mma_bf16(acc[mt][nt], ah[mt], bh[np][ps], bh[np][ps + 1]);
                }
        }
    }

    // Epilogue
    const int g = lane >> 2, t = lane & 3;
    #pragma unroll
    for (int mt = 0; mt < 2; mt++) {
        const int r0 = m0 + wm * 32 + mt * 16 + g;
        #pragma unroll
        for (int nt = 0; nt < 8; nt++) {
            const int col = n0 + wn * 64 + nt * 8 + 2 * t;
            float v0 = acc[mt][nt][0], v1 = acc[mt][nt][1];
            float v2 = acc[mt][nt][2], v3 = acc[mt][nt][3];
            if (MODE == 2) {
                float* d0 = Cf + (long)z * sC + (long)r0 * ldc + coff + col;
                float* d1 = d0 + (long)8 * ldc;
                *reinterpret_cast<float2*>(d0) = make_float2(v0, v1);
                *reinterpret_cast<float2*>(d1) = make_float2(v2, v3);
            } else if (MODE == 1) {
                // bf16 scores (scaled)
                __nv_bfloat162 p0, p1;
                p0.x = __float2bfloat16(v0 * scale); p0.y = __float2bfloat16(v1 * scale);
                p1.x = __float2bfloat16(v2 * scale); p1.y = __float2bfloat16(v3 * scale);
                __nv_bfloat16* dh0 = Chi + (long)z * sQ + (long)r0 * ldq + col;
                *reinterpret_cast<__nv_bfloat162*>(dh0) = p0;
                *reinterpret_cast<__nv_bfloat162*>(dh0 + 8 * ldq) = p1;
            } else {
                const float2 bv = *reinterpret_cast<const float2*>(bias + col);
                __nv_bfloat162 p0, p1;
                p0.x = __float2bfloat16(v0 + bv.x); p0.y = __float2bfloat16(v1 + bv.y);
                p1.x = __float2bfloat16(v2 + bv.x); p1.y = __float2bfloat16(v3 + bv.y);
                __nv_bfloat16* dh0 = Chi + (long)z * sQ + (long)r0 * ldq + col;
                *reinterpret_cast<__nv_bfloat162*>(dh0) = p0;
                *reinterpret_cast<__nv_bfloat162*>(dh0 + 8 * ldq) = p1;
            }
        }
    }
}

// ---------------------------------------------------------------------------
// Per-batch mask prefix scan: qvalid (packed->orig) and Lv.
// ---------------------------------------------------------------------------
__global__ void mask_scan(const int* __restrict__ qm,
                          int* __restrict__ qvalid, int* __restrict__ Lv)
{
    const int b = blockIdx.x, t = threadIdx.x;
    __shared__ int sc[256];
    const int* m = qm + (long)b * kLQ;
    int mv[4];
    #pragma unroll
    for (int i = 0; i < 4; i++) mv[i] = m[t * 4 + i];
    const int c = mv[0] + mv[1] + mv[2] + mv[3];
    sc[t] = c;
    __syncthreads();
    for (int off = 1; off < 256; off <<= 1) {
        const int v = (t >= off) ? sc[t - off] : 0;
        __syncthreads();
        sc[t] += v;
        __syncthreads();
    }
    int exc = sc[t] - c;
    int* qv = qvalid + (long)b * kLQ;
    #pragma unroll
    for (int i = 0; i < 4; i++) {
        const int q = t * 4 + i;
        if (mv[i]) { qv[exc] = q; exc++; }
    }
    if (t == 255) Lv[b] = sc[255];
}

// ---------------------------------------------------------------------------
// qh -> (a) packed bf16 rows [B, packed_q, D]   (K1's A operand)
//       (b) packed transposed [B, D, packed_q]  (K4's B operand)
// ---------------------------------------------------------------------------
__global__ void gather_pack(const float* __restrict__ in,
                            const int* __restrict__ qvalid,
                            const int* __restrict__ LvArr,
                            __nv_bfloat16* __restrict__ pk,
                            __nv_bfloat16* __restrict__ oT)
{
    const int b  = blockIdx.z;
    const int lv = __ldg(&LvArr[b]);
    const int q0 = blockIdx.y * 32;               // packed row tile
    if (q0 >= ((lv + 127) & ~127)) return;
    const int d0 = blockIdx.x * 32;
    const int tx = threadIdx.x, ty = threadIdx.y;

    __shared__ float t[32][33];
    __shared__ int src[32];
    if (ty == 0) {
        const int j = q0 + tx;
        src[tx] = (j < lv) ? __ldg(&qvalid[b * kLQ + j]) : -1;
    }
    __syncthreads();

    const float* ib = in + (long)b * kLQ * kD;
    __nv_bfloat16* pb = pk + (long)b * kLQ * kD;
    #pragma unroll
    for (int j = 0; j < 4; j++) {
        const int row = ty + 8 * j;               // packed row within tile
        const int sq  = src[row];
        const float v = (sq >= 0) ? ib[(long)sq * kD + d0 + tx] : 0.f;
        t[row][tx] = v;
        pb[(long)(q0 + row) * kD + d0 + tx] = __float2bfloat16(v);
    }
    __syncthreads();
    __nv_bfloat16* bh = oT + (long)b * kD * kLQ;
    #pragma unroll
    for (int j = 0; j < 4; j++) {
        const float v = t[tx][ty + 8 * j];
        bh[(long)(d0 + ty + 8 * j) * kLQ + q0 + tx] = __float2bfloat16(v);
    }
}

// ---------------------------------------------------------------------------
// ctx: one read -> output first half copy + bf16 convert
// ---------------------------------------------------------------------------
__global__ void prep_ctx(const float* __restrict__ ctx, float* __restrict__ out,
                         __nv_bfloat16* __restrict__ hi)
{
    const int n4 = kB * kLC * (kD / 4);
    const int i = blockIdx.x * blockDim.x + threadIdx.x;
    if (i >= n4) return;
    const float4 v = reinterpret_cast<const float4*>(ctx)[i];
    const int row = i / (kD / 4);
    const int col = i - row * (kD / 4);
    reinterpret_cast<float4*>(out)[(long)row * (2 * kD / 4) + col] = v;
    __nv_bfloat162 p0; p0.x = __float2bfloat16(v.x); p0.y = __float2bfloat16(v.y);
    __nv_bfloat162 p1; p1.x = __float2bfloat16(v.z); p1.y = __float2bfloat16(v.w);
    reinterpret_cast<__nv_bfloat162*>(hi)[2*i+0] = p0;
    reinterpret_cast<__nv_bfloat162*>(hi)[2*i+1] = p1;
}

// ---------------------------------------------------------------------------
// fp32 -> bf16 convert (W)
// ---------------------------------------------------------------------------
__global__ void split_hi(const float* __restrict__ in,
                         __nv_bfloat16* __restrict__ hi, int n4)
{
    const int i = blockIdx.x * blockDim.x + threadIdx.x;
    if (i >= n4) return;
    const float4 v = reinterpret_cast<const float4*>(in)[i];
    __nv_bfloat162 p0; p0.x = __float2bfloat16(v.x); p0.y = __float2bfloat16(v.y);
    __nv_bfloat162 p1; p1.x = __float2bfloat16(v.z); p1.y = __float2bfloat16(v.w);
    reinterpret_cast<__nv_bfloat162*>(hi)[2*i+0] = p0;
    reinterpret_cast<__nv_bfloat162*>(hi)[2*i+1] = p1;
}

// ---------------------------------------------------------------------------
// Softmax over packed bf16 scores [0, Lv); writes p_hi zeros in [Lv, pad128).
// Batch offset handled by caller via pointer + LvArr offsets.
// ---------------------------------------------------------------------------
__global__ void softmax_packed(const __nv_bfloat16* __restrict__ scores,
                               const int* __restrict__ LvArr,
                               __nv_bfloat16* __restrict__ phi)
{
    const int row = blockIdx.x;              // 0 .. nb*LC-1 (local)
    const int b   = row >> 11;               // / kLC (local batch)
    const int lv  = __ldg(&LvArr[b]);
    const int lim = (lv + 127) & ~127;
    const __nv_bfloat16* s = scores + (long)row * kLQ;

    const int t = threadIdx.x;               // 256 threads, 4 elems each
    float v[4]; int ok[4];
    float mx = -1e30f;
    #pragma unroll
    for (int i = 0; i < 4; i++) {
        const int q = t + i * 256;
        ok[i] = (q < lv);
        v[i]  = ok[i] ? __bfloat162float(s[q]) : 0.f;
        if (ok[i]) mx = fmaxf(mx, v[i]);
    }

    __shared__ float smax[8];
    __shared__ float ssum[8];

    #pragma unroll
    for (int off = 16; off; off >>= 1)
        mx = fmaxf(mx, __shfl_xor_sync(0xffffffffu, mx, off));
    if ((t & 31) == 0) smax[t >> 5] = mx;
    __syncthreads();
    float bm = -1e30f;
    #pragma unroll
    for (int w = 0; w < 8; w++) bm = fmaxf(bm, smax[w]);

    float e[4];
    float sum = 0.f;
    #pragma unroll
    for (int i = 0; i < 4; i++) {
        e[i] = ok[i] ? __expf(v[i] - bm) : 0.f;
        sum += e[i];
    }
    #pragma unroll
    for (int off = 16; off; off >>= 1)
        sum += __shfl_xor_sync(0xffffffffu, sum, off);
    if ((t & 31) == 0) ssum[t >> 5] = sum;
    __syncthreads();
    float total = 0.f;
    #pragma unroll
    for (int w = 0; w < 8; w++) total += ssum[w];

    const float inv = 1.f / total;
    __nv_bfloat16* dh = phi + (long)row * kLQ;
    #pragma unroll
    for (int i = 0; i < 4; i++) {
        const int q = t + i * 256;
        if (q < lim) dh[q] = __float2bfloat16(e[i] * inv);   // 0 for q in [lv, lim)
    }
}

// ---------------------------------------------------------------------------
extern "C" void kernel_launch(void* const* d_in, const int* in_sizes, int n_in,
                              void* d_out, int out_size)
{
    const float* ctx  = (const float*)d_in[0];
    const float* qh   = (const float*)d_in[2];
    const int*   qm   = (const int*)d_in[3];
    const float* W    = (const float*)d_in[4];
    const float* bias = (const float*)d_in[5];
    float* out = (float*)d_out;
    (void)in_sizes; (void)n_in; (void)out_size;

    __nv_bfloat16 *ctx_hi, *qh_pk, *qhT_hi, *W_hi, *q_hi, *p_hi, *scores;
    int *qvalid, *Lv;
    cudaGetSymbolAddress((void**)&ctx_hi, g_ctx_hi);
    cudaGetSymbolAddress((void**)&qh_pk,  g_qh_pk);
    cudaGetSymbolAddress((void**)&qhT_hi, g_qhT_hi);
    cudaGetSymbolAddress((void**)&W_hi,   g_W_hi);
    cudaGetSymbolAddress((void**)&q_hi,   g_q_hi);
    cudaGetSymbolAddress((void**)&p_hi,   g_p_hi);
    cudaGetSymbolAddress((void**)&scores, g_scores);
    cudaGetSymbolAddress((void**)&qvalid, g_qvalid);
    cudaGetSymbolAddress((void**)&Lv,     g_Lv);

    // One-time resource setup (first call is the uncaptured correctness run;
    // captured calls then only record/wait on these — pure graph nodes).
    static cudaStream_t s1 = nullptr;
    static cudaEvent_t eFork = nullptr, eW = nullptr, eJoin = nullptr;
    static cudaEvent_t eQ = nullptr, eB = nullptr;
    if (s1 == nullptr) {
        cudaStreamCreateWithFlags(&s1, cudaStreamNonBlocking);
        cudaEventCreateWithFlags(&eFork, cudaEventDisableTiming);
        cudaEventCreateWithFlags(&eW,    cudaEventDisableTiming);
        cudaEventCreateWithFlags(&eJoin, cudaEventDisableTiming);
        cudaEventCreateWithFlags(&eQ,    cudaEventDisableTiming);
        cudaEventCreateWithFlags(&eB,    cudaEventDisableTiming);
        cudaFuncSetAttribute(gemm_tc<0>, cudaFuncAttributeMaxDynamicSharedMemorySize, SMEM_SZ);
        cudaFuncSetAttribute(gemm_tc<1>, cudaFuncAttributeMaxDynamicSharedMemorySize, SMEM_SZ);
        cudaFuncSetAttribute(gemm_tc<2>, cudaFuncAttributeMaxDynamicSharedMemorySize, SMEM_SZ);
    }

    const long sCtx = (long)kLC * kD;     // ctx batch stride
    const long sQd  = (long)kLQ * kD;     // query/qh batch stride
    const long sSc  = (long)kLC * kLQ;    // scores/probs batch stride
    const long sT   = (long)kD * kLQ;     // qhT batch stride
    const long sOut = (long)kLC * 2 * kD; // output batch stride
    const int  HB   = kB / 2;             // 4 batches per chain

    // Fork: side stream runs W convert then the ctx branch.
    cudaEventRecord(eFork, 0);
    cudaStreamWaitEvent(s1, eFork, 0);

    // Branch B (stream s1): W convert (tiny), then ctx copy+convert (HBM-bound).
    split_hi<<<(kD * kD / 4 + 255) / 256, 256, 0, s1>>>(W, W_hi, kD * kD / 4);
    cudaEventRecord(eW, s1);
    prep_ctx<<<(kB * kLC * (kD / 4) + 255) / 256, 256, 0, s1>>>(ctx, out, ctx_hi);
    cudaEventRecord(eJoin, s1);

    // Branch A (main stream): mask scan, qh gather/transpose, K1 (needs W).
    mask_scan<<<kB, 256>>>(qm, qvalid, Lv);
    gather_pack<<<dim3(kD / 32, kLQ / 32, kB), dim3(32, 8)>>>(qh, qvalid, Lv, qh_pk, qhT_hi);
    cudaStreamWaitEvent(0, eW, 0);
    gemm_tc<0><<<dim3(kD / 128, kLQ / 128, kB), 256, SMEM_SZ>>>(
        qh_pk, sQd, kD,
        W_hi, 0, kD, kD,
        nullptr, 0, 0, 0, 1.0f, bias,
        q_hi, sQd, kD, Lv);
    cudaEventRecord(eQ, 0);

    // ---- Dual-chain tail: chain A = batches [0,4) on main, chain B = [4,8) on s1.
    // Chain B (s1): already ordered after prep_ctx (ctx_hi); needs q_hi -> wait eQ.
    cudaStreamWaitEvent(s1, eQ, 0);
    gemm_tc<1><<<dim3(kLQ / 128, kLC / 128, HB), 256, SMEM_SZ, s1>>>(
        ctx_hi + HB * sCtx, sCtx, kD,
        q_hi + HB * sQd, sQd, kD, kD,
        nullptr, 0, 0, 0, kScale, nullptr,
        scores + HB * sSc, sSc, kLQ, Lv + HB);
    softmax_packed<<<HB * kLC, 256, 0, s1>>>(scores + HB * sSc, Lv + HB, p_hi + HB * sSc);
    gemm_tc<2><<<dim3(kD / 128, kLC / 128, HB), 256, SMEM_SZ, s1>>>(
        p_hi + HB * sSc, sSc, kLQ,
        qhT_hi + HB * sT, sT, kLQ, 0,
        out + HB * sOut, sOut, 2 * kD, kD, 1.0f, nullptr,
        nullptr, 0, 0, Lv + HB);
    cudaEventRecord(eB, s1);

    // Chain A (main): needs ctx_hi -> wait eJoin.
    cudaStreamWaitEvent(0, eJoin, 0);
    gemm_tc<1><<<dim3(kLQ / 128, kLC / 128, HB), 256, SMEM_SZ>>>(
        ctx_hi, sCtx, kD,
        q_hi, sQd, kD, kD,
        nullptr, 0, 0, 0, kScale, nullptr,
        scores, sSc, kLQ, Lv);
    softmax_packed<<<HB * kLC, 256>>>(scores, Lv, p_hi);
    gemm_tc<2><<<dim3(kD / 128, kLC / 128, HB), 256, SMEM_SZ>>>(
        p_hi, sSc, kLQ,
        qhT_hi, sT, kLQ, 0,
        out, sOut, 2 * kD, kD, 1.0f, nullptr,
        nullptr, 0, 0, Lv);

    // Join chain B into the capture stream.
    cudaStreamWaitEvent(0, eB, 0);
}

// round 17
// speedup vs baseline: 1.1368x; 1.0115x over previous
#include <cuda_runtime.h>
#include <cuda_bf16.h>
#include <cstdint>

// Problem constants (fixed shapes from setup_inputs)
static constexpr int kB  = 8;
static constexpr int kLC = 2048;
static constexpr int kLQ = 1024;
static constexpr int kD  = 768;
static constexpr float kScale = 0.036084391824351615f; // 1/sqrt(768)

// ---------------------------------------------------------------------------
// Scratch (__device__ globals; no allocs allowed) — pure bf16 pipeline
// ---------------------------------------------------------------------------
__device__ __nv_bfloat16 g_ctx_hi [(size_t)kB * kLC * kD];
__device__ __nv_bfloat16 g_qh_pk  [(size_t)kB * kLQ * kD];   // PACKED valid qh rows
__device__ __nv_bfloat16 g_qhT_hi [(size_t)kB * kD * kLQ];   // PACKED transposed
__device__ __nv_bfloat16 g_W_hi   [(size_t)kD * kD];
__device__ __nv_bfloat16 g_q_hi   [(size_t)kB * kLQ * kD];   // projected query (packed rows)
__device__ __nv_bfloat16 g_scores [(size_t)kB * kLC * kLQ];  // packed cols, bf16
__device__ __nv_bfloat16 g_p_hi   [(size_t)kB * kLC * kLQ];  // packed probs
__device__ int           g_qvalid [kB * kLQ];                // packed->orig q
__device__ int           g_Lv     [kB];                      // valid count per batch

// ---------------------------------------------------------------------------
// PTX helpers — base sm_103 instructions only (NO tcgen05 in this toolchain)
// ---------------------------------------------------------------------------
__device__ __forceinline__ uint32_t smem_u32(const void* p) {
    uint32_t a;
    asm("{ .reg .u64 t; cvta.to.shared.u64 t, %1; cvt.u32.u64 %0, t; }" : "=r"(a) : "l"(p));
    return a;
}
__device__ __forceinline__ void cp16(uint32_t dst, const void* src) {
    asm volatile("cp.async.cg.shared.global [%0], [%1], 16;" :: "r"(dst), "l"(src) : "memory");
}
__device__ __forceinline__ void cp_commit() { asm volatile("cp.async.commit_group;" ::: "memory"); }
template<int N> __device__ __forceinline__ void cp_wait() {
    asm volatile("cp.async.wait_group %0;" :: "n"(N) : "memory");
}
__device__ __forceinline__ void ldm4(uint32_t* r, uint32_t addr) {
    asm volatile("ldmatrix.sync.aligned.m8n8.x4.shared.b16 {%0,%1,%2,%3}, [%4];"
                 : "=r"(r[0]), "=r"(r[1]), "=r"(r[2]), "=r"(r[3]) : "r"(addr));
}
__device__ __forceinline__ void mma_bf16(float* c, const uint32_t* a, uint32_t b0, uint32_t b1) {
    asm volatile("mma.sync.aligned.m16n8k16.row.col.f32.bf16.bf16.f32 "
                 "{%0,%1,%2,%3}, {%4,%5,%6,%7}, {%8,%9}, {%0,%1,%2,%3};"
                 : "+f"(c[0]), "+f"(c[1]), "+f"(c[2]), "+f"(c[3])
                 : "r"(a[0]), "r"(a[1]), "r"(a[2]), "r"(a[3]), "r"(b0), "r"(b1));
}

// ---------------------------------------------------------------------------
// Tensor-core NT GEMM, single-term bf16, fp32 accumulate: acc = A*B^T
// CTA tile 128x128, BK=32, 4-stage cp.async pipeline (2 arrays/stage = 80KB),
// 8 warps (4Mx2N), warp tile 32x64, 2 CTAs/SM, ONE barrier per stage.
// Batch offset handled by caller via pointer + LvArr offsets (dual-chain).
// MODE 0 (K1): batched A; M-early-exit at pad128(Lv[z]); +bias; out -> bf16
// MODE 1 (K2): N-early-exit at Lv[z]; out = bf16(acc*scale) -> Chi (scores)
// MODE 2 (K4): runtime K=pad128(Lv[z]); out=acc fp32 at [.., coff+col]
// ---------------------------------------------------------------------------
static constexpr int ARR_B   = 10240;      // 128 rows * 80B (64B data + 16B pad)
static constexpr int STAGE_B = 2 * ARR_B;  // A, B
static constexpr int NSTAGE  = 4;
static constexpr int SMEM_SZ = NSTAGE * STAGE_B;  // 81920

template<int MODE>
__global__ void __launch_bounds__(256, 2)
gemm_tc(const __nv_bfloat16* __restrict__ Ahi, long sA, int lda,
        const __nv_bfloat16* __restrict__ Bhi, long sB, int ldb, int Kstatic,
        float* __restrict__ Cf, long sC, int ldc, int coff, float scale,
        const float* __restrict__ bias,
        __nv_bfloat16* __restrict__ Chi, long sQ, int ldq,
        const int* __restrict__ LvArr)
{
    const int z  = blockIdx.z;
    const int m0 = blockIdx.y * 128;
    const int n0 = blockIdx.x * 128;

    const int lv = __ldg(&LvArr[z]);
    if (MODE == 0 && m0 >= ((lv + 127) & ~127)) return;   // only packed query rows
    if (MODE == 1 && n0 >= lv) return;                    // only valid q columns

    int Ktot = Kstatic;
    if (MODE == 2) Ktot = (lv + 127) & ~127;

    extern __shared__ __align__(128) char dsm[];
    const uint32_t base = smem_u32(dsm);

    const int tid  = threadIdx.x;
    const int wid  = tid >> 5;
    const int lane = tid & 31;
    const int wm   = wid & 3;
    const int wn   = wid >> 2;

    const __nv_bfloat16* pAh = Ahi + (long)z * sA + (long)m0 * lda;
    const __nv_bfloat16* pBh = Bhi + (long)z * sB + (long)n0 * ldb;

    const int S = Ktot >> 5;           // BK=32 stages (>=4 always)

    auto load_stage = [&](int s) {
        const uint32_t sb = base + (uint32_t)(s & (NSTAGE - 1)) * STAGE_B;
        const int k0 = s << 5;
        const int r  = tid >> 2;
        const int ch = tid & 3;
        cp16(sb + r * 80 + ch * 16,        pAh + (long)r * lda + k0 + ch * 8);
        cp16(sb + (r + 64) * 80 + ch * 16, pAh + (long)(r + 64) * lda + k0 + ch * 8);
        cp16(sb + ARR_B + r * 80 + ch * 16,        pBh + (long)r * ldb + k0 + ch * 8);
        cp16(sb + ARR_B + (r + 64) * 80 + ch * 16, pBh + (long)(r + 64) * ldb + k0 + ch * 8);
        cp_commit();
    };

    // ldmatrix per-lane address components
    const int ati = lane >> 3;
    const int a_row = (lane & 7) + (ati & 1) * 8;
    const int a_col = (ati >> 1) * 16;
    const uint32_t a_base = (uint32_t)((wm * 32 + a_row) * 80 + a_col);
    const int b_row = (ati >> 1) * 8 + (lane & 7);
    const int b_col = (ati & 1) * 16;
    const uint32_t b_base = (uint32_t)((wn * 64 + b_row) * 80 + b_col);

    float acc[2][8][4];
    #pragma unroll
    for (int mt = 0; mt < 2; mt++)
        #pragma unroll
        for (int nt = 0; nt < 8; nt++)
            #pragma unroll
            for (int r = 0; r < 4; r++) acc[mt][nt][r] = 0.f;

    load_stage(0);
    load_stage(1);
    load_stage(2);

    for (int s = 0; s < S; s++) {
        const int rem = S - 1 - s;
        if (rem >= 2) cp_wait<2>(); else if (rem == 1) cp_wait<1>(); else cp_wait<0>();
        __syncthreads();                    // single barrier per stage
        if (s + 3 < S) load_stage(s + 3);

        const uint32_t sb = base + (uint32_t)(s & (NSTAGE - 1)) * STAGE_B;
        #pragma unroll
        for (int ks = 0; ks < 2; ks++) {
            uint32_t ah[2][4];
            #pragma unroll
            for (int mt = 0; mt < 2; mt++)
                ldm4(ah[mt], sb + a_base + (uint32_t)(mt * 16 * 80 + ks * 32));
            uint32_t bh[4][4];
            #pragma unroll
            for (int np = 0; np < 4; np++)
                ldm4(bh[np], sb + ARR_B + b_base + (uint32_t)(np * 16 * 80 + ks * 32));
            #pragma unroll
            for (int mt = 0; mt < 2; mt++)
                #pragma unroll
                for (int nt = 0; nt < 8; nt++) {
                    const int np = nt >> 1, ps = (nt & 1) * 2;
                    mma_bf16(acc[mt][nt], ah[mt], bh[np][ps], bh[np][ps + 1]);
                }
        }
    }

    // Epilogue
    const int g = lane >> 2, t = lane & 3;
    #pragma unroll
    for (int mt = 0; mt < 2; mt++) {
        const int r0 = m0 + wm * 32 + mt * 16 + g;
        #pragma unroll
        for (int nt = 0; nt < 8; nt++) {
            const int col = n0 + wn * 64 + nt * 8 + 2 * t;
            float v0 = acc[mt][nt][0], v1 = acc[mt][nt][1];
            float v2 = acc[mt][nt][2], v3 = acc[mt][nt][3];
            if (MODE == 2) {
                float* d0 = Cf + (long)z * sC + (long)r0 * ldc + coff + col;
                float* d1 = d0 + (long)8 * ldc;
                *reinterpret_cast<float2*>(d0) = make_float2(v0, v1);
                *reinterpret_cast<float2*>(d1) = make_float2(v2, v3);
            } else if (MODE == 1) {
                // bf16 scores (scaled)
                __nv_bfloat162 p0, p1;
                p0.x = __float2bfloat16(v0 * scale); p0.y = __float2bfloat16(v1 * scale);
                p1.x = __float2bfloat16(v2 * scale); p1.y = __float2bfloat16(v3 * scale);
                __nv_bfloat16* dh0 = Chi + (long)z * sQ + (long)r0 * ldq + col;
                *reinterpret_cast<__nv_bfloat162*>(dh0) = p0;
                *reinterpret_cast<__nv_bfloat162*>(dh0 + 8 * ldq) = p1;
            } else {
                const float2 bv = *reinterpret_cast<const float2*>(bias + col);
                __nv_bfloat162 p0, p1;
                p0.x = __float2bfloat16(v0 + bv.x); p0.y = __float2bfloat16(v1 + bv.y);
                p1.x = __float2bfloat16(v2 + bv.x); p1.y = __float2bfloat16(v3 + bv.y);
                __nv_bfloat16* dh0 = Chi + (long)z * sQ + (long)r0 * ldq + col;
                *reinterpret_cast<__nv_bfloat162*>(dh0) = p0;
                *reinterpret_cast<__nv_bfloat162*>(dh0 + 8 * ldq) = p1;
            }
        }
    }
}

// ---------------------------------------------------------------------------
// Per-batch mask prefix scan: qvalid (packed->orig) and Lv.
// ---------------------------------------------------------------------------
__global__ void mask_scan(const int* __restrict__ qm,
                          int* __restrict__ qvalid, int* __restrict__ Lv)
{
    const int b = blockIdx.x, t = threadIdx.x;
    __shared__ int sc[256];
    const int* m = qm + (long)b * kLQ;
    int mv[4];
    #pragma unroll
    for (int i = 0; i < 4; i++) mv[i] = m[t * 4 + i];
    const int c = mv[0] + mv[1] + mv[2] + mv[3];
    sc[t] = c;
    __syncthreads();
    for (int off = 1; off < 256; off <<= 1) {
        const int v = (t >= off) ? sc[t - off] : 0;
        __syncthreads();
        sc[t] += v;
        __syncthreads();
    }
    int exc = sc[t] - c;
    int* qv = qvalid + (long)b * kLQ;
    #pragma unroll
    for (int i = 0; i < 4; i++) {
        const int q = t * 4 + i;
        if (mv[i]) { qv[exc] = q; exc++; }
    }
    if (t == 255) Lv[b] = sc[255];
}

// ---------------------------------------------------------------------------
// qh -> (a) packed bf16 rows [nb, packed_q, D]   (K1's A operand)
//       (b) packed transposed [nb, D, packed_q]  (K4's B operand)
// All pointers pre-offset by caller for the chain's batch range.
// ---------------------------------------------------------------------------
__global__ void gather_pack(const float* __restrict__ in,
                            const int* __restrict__ qvalid,
                            const int* __restrict__ LvArr,
                            __nv_bfloat16* __restrict__ pk,
                            __nv_bfloat16* __restrict__ oT)
{
    const int b  = blockIdx.z;
    const int lv = __ldg(&LvArr[b]);
    const int q0 = blockIdx.y * 32;               // packed row tile
    if (q0 >= ((lv + 127) & ~127)) return;
    const int d0 = blockIdx.x * 32;
    const int tx = threadIdx.x, ty = threadIdx.y;

    __shared__ float t[32][33];
    __shared__ int src[32];
    if (ty == 0) {
        const int j = q0 + tx;
        src[tx] = (j < lv) ? __ldg(&qvalid[b * kLQ + j]) : -1;
    }
    __syncthreads();

    const float* ib = in + (long)b * kLQ * kD;
    __nv_bfloat16* pb = pk + (long)b * kLQ * kD;
    #pragma unroll
    for (int j = 0; j < 4; j++) {
        const int row = ty + 8 * j;               // packed row within tile
        const int sq  = src[row];
        const float v = (sq >= 0) ? ib[(long)sq * kD + d0 + tx] : 0.f;
        t[row][tx] = v;
        pb[(long)(q0 + row) * kD + d0 + tx] = __float2bfloat16(v);
    }
    __syncthreads();
    __nv_bfloat16* bh = oT + (long)b * kD * kLQ;
    #pragma unroll
    for (int j = 0; j < 4; j++) {
        const float v = t[tx][ty + 8 * j];
        bh[(long)(d0 + ty + 8 * j) * kLQ + q0 + tx] = __float2bfloat16(v);
    }
}

// ---------------------------------------------------------------------------
// ctx: one read -> output first half copy + bf16 convert (n4 float4 elems;
// pointers pre-offset by caller for the chain's batch range).
// ---------------------------------------------------------------------------
__global__ void prep_ctx(const float* __restrict__ ctx, float* __restrict__ out,
                         __nv_bfloat16* __restrict__ hi, int n4)
{
    const int i = blockIdx.x * blockDim.x + threadIdx.x;
    if (i >= n4) return;
    const float4 v = reinterpret_cast<const float4*>(ctx)[i];
    const int row = i / (kD / 4);
    const int col = i - row * (kD / 4);
    reinterpret_cast<float4*>(out)[(long)row * (2 * kD / 4) + col] = v;
    __nv_bfloat162 p0; p0.x = __float2bfloat16(v.x); p0.y = __float2bfloat16(v.y);
    __nv_bfloat162 p1; p1.x = __float2bfloat16(v.z); p1.y = __float2bfloat16(v.w);
    reinterpret_cast<__nv_bfloat162*>(hi)[2*i+0] = p0;
    reinterpret_cast<__nv_bfloat162*>(hi)[2*i+1] = p1;
}

// ---------------------------------------------------------------------------
// fp32 -> bf16 convert (W)
// ---------------------------------------------------------------------------
__global__ void split_hi(const float* __restrict__ in,
                         __nv_bfloat16* __restrict__ hi, int n4)
{
    const int i = blockIdx.x * blockDim.x + threadIdx.x;
    if (i >= n4) return;
    const float4 v = reinterpret_cast<const float4*>(in)[i];
    __nv_bfloat162 p0; p0.x = __float2bfloat16(v.x); p0.y = __float2bfloat16(v.y);
    __nv_bfloat162 p1; p1.x = __float2bfloat16(v.z); p1.y = __float2bfloat16(v.w);
    reinterpret_cast<__nv_bfloat162*>(hi)[2*i+0] = p0;
    reinterpret_cast<__nv_bfloat162*>(hi)[2*i+1] = p1;
}

// ---------------------------------------------------------------------------
// Softmax over packed bf16 scores [0, Lv); writes p_hi zeros in [Lv, pad128).
// Pointers pre-offset for the chain's batch range.
// ---------------------------------------------------------------------------
__global__ void softmax_packed(const __nv_bfloat16* __restrict__ scores,
                               const int* __restrict__ LvArr,
                               __nv_bfloat16* __restrict__ phi)
{
    const int row = blockIdx.x;              // 0 .. nb*LC-1 (local)
    const int b   = row >> 11;               // / kLC (local batch)
    const int lv  = __ldg(&LvArr[b]);
    const int lim = (lv + 127) & ~127;
    const __nv_bfloat16* s = scores + (long)row * kLQ;

    const int t = threadIdx.x;               // 256 threads, 4 elems each
    float v[4]; int ok[4];
    float mx = -1e30f;
    #pragma unroll
    for (int i = 0; i < 4; i++) {
        const int q = t + i * 256;
        ok[i] = (q < lv);
        v[i]  = ok[i] ? __bfloat162float(s[q]) : 0.f;
        if (ok[i]) mx = fmaxf(mx, v[i]);
    }

    __shared__ float smax[8];
    __shared__ float ssum[8];

    #pragma unroll
    for (int off = 16; off; off >>= 1)
        mx = fmaxf(mx, __shfl_xor_sync(0xffffffffu, mx, off));
    if ((t & 31) == 0) smax[t >> 5] = mx;
    __syncthreads();
    float bm = -1e30f;
    #pragma unroll
    for (int w = 0; w < 8; w++) bm = fmaxf(bm, smax[w]);

    float e[4];
    float sum = 0.f;
    #pragma unroll
    for (int i = 0; i < 4; i++) {
        e[i] = ok[i] ? __expf(v[i] - bm) : 0.f;
        sum += e[i];
    }
    #pragma unroll
    for (int off = 16; off; off >>= 1)
        sum += __shfl_xor_sync(0xffffffffu, sum, off);
    if ((t & 31) == 0) ssum[t >> 5] = sum;
    __syncthreads();
    float total = 0.f;
    #pragma unroll
    for (int w = 0; w < 8; w++) total += ssum[w];

    const float inv = 1.f / total;
    __nv_bfloat16* dh = phi + (long)row * kLQ;
    #pragma unroll
    for (int i = 0; i < 4; i++) {
        const int q = t + i * 256;
        if (q < lim) dh[q] = __float2bfloat16(e[i] * inv);   // 0 for q in [lv, lim)
    }
}

// ---------------------------------------------------------------------------
extern "C" void kernel_launch(void* const* d_in, const int* in_sizes, int n_in,
                              void* d_out, int out_size)
{
    const float* ctx  = (const float*)d_in[0];
    const float* qh   = (const float*)d_in[2];
    const int*   qm   = (const int*)d_in[3];
    const float* W    = (const float*)d_in[4];
    const float* bias = (const float*)d_in[5];
    float* out = (float*)d_out;
    (void)in_sizes; (void)n_in; (void)out_size;

    __nv_bfloat16 *ctx_hi, *qh_pk, *qhT_hi, *W_hi, *q_hi, *p_hi, *scores;
    int *qvalid, *Lv;
    cudaGetSymbolAddress((void**)&ctx_hi, g_ctx_hi);
    cudaGetSymbolAddress((void**)&qh_pk,  g_qh_pk);
    cudaGetSymbolAddress((void**)&qhT_hi, g_qhT_hi);
    cudaGetSymbolAddress((void**)&W_hi,   g_W_hi);
    cudaGetSymbolAddress((void**)&q_hi,   g_q_hi);
    cudaGetSymbolAddress((void**)&p_hi,   g_p_hi);
    cudaGetSymbolAddress((void**)&scores, g_scores);
    cudaGetSymbolAddress((void**)&qvalid, g_qvalid);
    cudaGetSymbolAddress((void**)&Lv,     g_Lv);

    // One-time resource setup (first call is the uncaptured correctness run;
    // captured calls then only record/wait on these — pure graph nodes).
    static cudaStream_t s1 = nullptr, s2 = nullptr;
    static cudaEvent_t eFork = nullptr, eW = nullptr, eM = nullptr;
    static cudaEvent_t eCtxA = nullptr, eCtxB = nullptr, eB = nullptr;
    if (s1 == nullptr) {
        cudaStreamCreateWithFlags(&s1, cudaStreamNonBlocking);
        cudaStreamCreateWithFlags(&s2, cudaStreamNonBlocking);
        cudaEventCreateWithFlags(&eFork, cudaEventDisableTiming);
        cudaEventCreateWithFlags(&eW,    cudaEventDisableTiming);
        cudaEventCreateWithFlags(&eM,    cudaEventDisableTiming);
        cudaEventCreateWithFlags(&eCtxA, cudaEventDisableTiming);
        cudaEventCreateWithFlags(&eCtxB, cudaEventDisableTiming);
        cudaEventCreateWithFlags(&eB,    cudaEventDisableTiming);
        cudaFuncSetAttribute(gemm_tc<0>, cudaFuncAttributeMaxDynamicSharedMemorySize, SMEM_SZ);
        cudaFuncSetAttribute(gemm_tc<1>, cudaFuncAttributeMaxDynamicSharedMemorySize, SMEM_SZ);
        cudaFuncSetAttribute(gemm_tc<2>, cudaFuncAttributeMaxDynamicSharedMemorySize, SMEM_SZ);
    }

    const long sCtx = (long)kLC * kD;     // ctx batch stride
    const long sQd  = (long)kLQ * kD;     // query/qh batch stride
    const long sSc  = (long)kLC * kLQ;    // scores/probs batch stride
    const long sT   = (long)kD * kLQ;     // qhT batch stride
    const long sOut = (long)kLC * 2 * kD; // output batch stride
    const int  HB   = kB / 2;             // 4 batches per chain
    const int  n4H  = HB * kLC * (kD / 4);

    // Fork
    cudaEventRecord(eFork, 0);
    cudaStreamWaitEvent(s1, eFork, 0);
    cudaStreamWaitEvent(s2, eFork, 0);

    // s2: ctx copy+convert, split per chain half (HBM-bound, off critical path).
    prep_ctx<<<(n4H + 255) / 256, 256, 0, s2>>>(ctx, out, ctx_hi, n4H);
    cudaEventRecord(eCtxA, s2);
    prep_ctx<<<(n4H + 255) / 256, 256, 0, s2>>>(ctx + HB * sCtx, out + HB * sOut,
                                                ctx_hi + HB * sCtx, n4H);
    cudaEventRecord(eCtxB, s2);

    // Chain A (main stream), batches [0, 4):
    mask_scan<<<kB, 256>>>(qm, qvalid, Lv);
    cudaEventRecord(eM, 0);
    gather_pack<<<dim3(kD / 32, kLQ / 32, HB), dim3(32, 8)>>>(
        qh, qvalid, Lv, qh_pk, qhT_hi);

    // Chain B (s1), batches [4, 8): W convert first, then its own front.
    split_hi<<<(kD * kD / 4 + 255) / 256, 256, 0, s1>>>(W, W_hi, kD * kD / 4);
    cudaEventRecord(eW, s1);
    cudaStreamWaitEvent(s1, eM, 0);
    gather_pack<<<dim3(kD / 32, kLQ / 32, HB), dim3(32, 8), 0, s1>>>(
        qh + HB * sQd, qvalid + HB * kLQ, Lv + HB,
        qh_pk + HB * sQd, qhT_hi + HB * sT);
    gemm_tc<0><<<dim3(kD / 128, kLQ / 128, HB), 256, SMEM_SZ, s1>>>(
        qh_pk + HB * sQd, sQd, kD,
        W_hi, 0, kD, kD,
        nullptr, 0, 0, 0, 1.0f, bias,
        q_hi + HB * sQd, sQd, kD, Lv + HB);
    cudaStreamWaitEvent(s1, eCtxB, 0);
    gemm_tc<1><<<dim3(kLQ / 128, kLC / 128, HB), 256, SMEM_SZ, s1>>>(
        ctx_hi + HB * sCtx, sCtx, kD,
        q_hi + HB * sQd, sQd, kD, kD,
        nullptr, 0, 0, 0, kScale, nullptr,
        scores + HB * sSc, sSc, kLQ, Lv + HB);
    softmax_packed<<<HB * kLC, 256, 0, s1>>>(scores + HB * sSc, Lv + HB, p_hi + HB * sSc);
    gemm_tc<2><<<dim3(kD / 128, kLC / 128, HB), 256, SMEM_SZ, s1>>>(
        p_hi + HB * sSc, sSc, kLQ,
        qhT_hi + HB * sT, sT, kLQ, 0,
        out + HB * sOut, sOut, 2 * kD, kD, 1.0f, nullptr,
        nullptr, 0, 0, Lv + HB);
    cudaEventRecord(eB, s1);

    // Chain A continued (main): K1 needs W (eW), K2 needs ctx_hi A (eCtxA).
    cudaStreamWaitEvent(0, eW, 0);
    gemm_tc<0><<<dim3(kD / 128, kLQ / 128, HB), 256, SMEM_SZ>>>(
        qh_pk, sQd, kD,
        W_hi, 0, kD, kD,
        nullptr, 0, 0, 0, 1.0f, bias,
        q_hi, sQd, kD, Lv);
    cudaStreamWaitEvent(0, eCtxA, 0);
    gemm_tc<1><<<dim3(kLQ / 128, kLC / 128, HB), 256, SMEM_SZ>>>(
        ctx_hi, sCtx, kD,
        q_hi, sQd, kD, kD,
        nullptr, 0, 0, 0, kScale, nullptr,
        scores, sSc, kLQ, Lv);
    softmax_packed<<<HB * kLC, 256>>>(scores, Lv, p_hi);
    gemm_tc<2><<<dim3(kD / 128, kLC / 128, HB), 256, SMEM_SZ>>>(
        p_hi, sSc, kLQ,
        qhT_hi, sT, kLQ, 0,
        out, sOut, 2 * kD, kD, 1.0f, nullptr,
        nullptr, 0, 0, Lv);

    // Join chain B into the capture stream.
    cudaStreamWaitEvent(0, eB, 0);
}